// round 5
// baseline (speedup 1.0000x reference)
#include <cuda_runtime.h>
#include <math.h>

// ---------------------------------------------------------------------------
// AttentiveBimodalCSRPool — round 5.
//  * strided-column weight layout: sWT[c*LDW+k] (LDW%32==4) + cols c=tx+8j
//    -> 1-wavefront LDS.128 weight fetches -> fma-bound micro-loop.
//  * BN1 stats via covariance SYRK (mu bug FIXED: no 0.25 factor).
//  * fused gemm1->bn1->relu->gemm2 in one kernel (dynamic smem 50.7KB).
//  * algebraic fold of score GEMM through weights (rounds 2-4).
// ---------------------------------------------------------------------------

#define MAXV 1000000
#define MAXN 125056
typedef unsigned long long ull;

__device__ float g_Y2[(size_t)MAXV * 64];
__device__ float g_R[(size_t)MAXN * 192];
__device__ float g_c[MAXN];
__device__ float g_X[MAXV];
__device__ int   g_seg[MAXV];
__device__ float g_stats[256];    // [128..191]=sum2, [192..255]=sq2
__device__ float g_cov[32 * 32];
__device__ float g_mu[32];
__device__ float g_bn1[128];      // [scale(64), shift(64)]
__device__ float g_bn2[128];
__device__ float g_Acmb[64 * 192];
__device__ float g_r0[192];
__device__ float g_wc[64];
__device__ float g_c0[1];

// ---- packed f32x2 helpers -------------------------------------------------
__device__ __forceinline__ ull pk2(float lo, float hi) {
    ull r; asm("mov.b64 %0, {%1, %2};" : "=l"(r) : "f"(lo), "f"(hi)); return r;
}
__device__ __forceinline__ ull fma2(ull a, ull b, ull c) {
    ull d; asm("fma.rn.f32x2 %0, %1, %2, %3;" : "=l"(d) : "l"(a), "l"(b), "l"(c));
    return d;
}
__device__ __forceinline__ void upk2(ull v, float& lo, float& hi) {
    asm("mov.b64 {%0, %1}, %2;" : "=f"(lo), "=f"(hi) : "l"(v));
}

// ---- row-major A tile loader: sX[r*LD + k], LD odd ------------------------
template <int K, int LD, int NT>
__device__ __forceinline__ void load_rm(const float* __restrict__ src,
                                        int row0, int limit,
                                        int srcStride, int srcOff,
                                        float* __restrict__ sX, int tid) {
    constexpr int K4 = K / 4;
    for (int t = tid; t < 128 * K4; t += NT) {
        int c4 = t % K4;
        int r  = t / K4;
        int row = row0 + r;
        float4 x = make_float4(0.f, 0.f, 0.f, 0.f);
        if (row < limit)
            x = *reinterpret_cast<const float4*>(&src[(size_t)row * srcStride + srcOff + c4 * 4]);
        float* d = &sX[r * LD + c4 * 4];
        d[0] = x.x; d[1] = x.y; d[2] = x.z; d[3] = x.w;
    }
}

// ---- core micro-step: one 4-k chunk, strided cols -------------------------
// acc[r][p]: pair p holds cols (tx+16p, tx+16p+8).
template <int LDX, int LDW>
__device__ __forceinline__ void mm_chunk(const float* __restrict__ sX,
                                         const float* __restrict__ sWT,
                                         ull acc[8][4], int tx, int r0, int k4) {
    float4 w4[8];
#pragma unroll
    for (int j = 0; j < 8; ++j)
        w4[j] = *reinterpret_cast<const float4*>(&sWT[(tx + 8 * j) * LDW + k4 * 4]);
    const float* wv = reinterpret_cast<const float*>(w4);
#pragma unroll
    for (int kk = 0; kk < 4; ++kk) {
        ull wp0 = pk2(wv[0 * 4 + kk], wv[1 * 4 + kk]);
        ull wp1 = pk2(wv[2 * 4 + kk], wv[3 * 4 + kk]);
        ull wp2 = pk2(wv[4 * 4 + kk], wv[5 * 4 + kk]);
        ull wp3 = pk2(wv[6 * 4 + kk], wv[7 * 4 + kk]);
#pragma unroll
        for (int r = 0; r < 8; ++r) {
            float a = sX[(r0 + r) * LDX + k4 * 4 + kk];
            ull ap = pk2(a, a);
            acc[r][0] = fma2(ap, wp0, acc[r][0]);
            acc[r][1] = fma2(ap, wp1, acc[r][1]);
            acc[r][2] = fma2(ap, wp2, acc[r][2]);
            acc[r][3] = fma2(ap, wp3, acc[r][3]);
        }
    }
}

// ---------------------------------------------------------------------------
__global__ void k_zero() {
    int t = threadIdx.x + blockIdx.x * blockDim.x;
    if (t < 128) g_stats[128 + t] = 0.f;
    if (t < 1024) g_cov[t] = 0.f;
    if (t < 32) g_mu[t] = 0.f;
}

__global__ void k_seg(const int* __restrict__ csr, int N) {
    int n = blockIdx.x * blockDim.x + threadIdx.x;
    if (n < N) {
        int s = csr[n], e = csr[n + 1];
        for (int v = s; v < e; ++v) g_seg[v] = n;
    }
}

// ---- combined weights: Acmb = Wq@Wk^T, r0, wc, c0 -------------------------
__global__ __launch_bounds__(256) void k_prep(const float* __restrict__ Wq,
                                              const float* __restrict__ bq,
                                              const float* __restrict__ Wk,
                                              const float* __restrict__ bk) {
    __shared__ float sWq[64 * 64];
    __shared__ float sWk[64 * 65];
    __shared__ float sbq[64], sbk[64];
    int tid = threadIdx.x;
    for (int i = tid; i < 64 * 64; i += 256) sWq[i] = Wq[i];
    if (tid < 64) { sbq[tid] = bq[tid]; sbk[tid] = bk[tid]; }
    __syncthreads();
    int irow = tid >> 6;
    int jl   = tid & 63;
    for (int cc = 0; cc < 3; ++cc) {
        __syncthreads();
        for (int t = tid; t < 64 * 64; t += 256) {
            int jj = t >> 6, s = t & 63;
            sWk[jj * 65 + s] = Wk[(cc * 64 + jj) * 64 + s];
        }
        __syncthreads();
#pragma unroll 4
        for (int it = 0; it < 16; ++it) {
            int ii = it * 4 + irow;
            float a = 0.f;
#pragma unroll 8
            for (int s = 0; s < 64; ++s)
                a = fmaf(sWq[ii * 64 + s], sWk[jl * 65 + s], a);
            g_Acmb[ii * 192 + cc * 64 + jl] = a;
        }
        if (tid < 64) {
            float a = 0.f;
#pragma unroll 8
            for (int s = 0; s < 64; ++s) a = fmaf(sbq[s], sWk[tid * 65 + s], a);
            g_r0[cc * 64 + tid] = a;
        }
    }
    if (tid < 64) {
        float a = 0.f;
#pragma unroll 8
        for (int s = 0; s < 64; ++s) a = fmaf(sWq[tid * 64 + s], sbk[s], a);
        g_wc[tid] = a;
    }
    if (tid == 0) {
        float a = 0.f;
        for (int s = 0; s < 64; ++s) a = fmaf(sbq[s], sbk[s], a);
        g_c0[0] = a;
    }
}

// ---- SYRK: g_cov += x_proj^T x_proj, g_mu += colsum (FIXED) ---------------
__global__ __launch_bounds__(256) void k_cov(const float* __restrict__ xproj, int V) {
    __shared__ __align__(16) float sX[128 * 33];
    __shared__ float sCov[1024];
    __shared__ float sMu[32];
    int tid = threadIdx.x;
    for (int t = tid; t < 1024; t += 256) sCov[t] = 0.f;
    if (tid < 32) sMu[tid] = 0.f;

    int i4 = tid & 7;
    int j4 = (tid >> 3) & 7;
    int rs = tid >> 6;
    ull acc[4][2] = {};
    float musum = 0.f;
    int base = blockIdx.x * 512;

    for (int tile = 0; tile < 4; ++tile) {
        __syncthreads();
        load_rm<32, 33, 256>(xproj, base + tile * 128, V, 32, 0, sX, tid);
        __syncthreads();
        int rbeg = rs * 32;
#pragma unroll 4
        for (int r = rbeg; r < rbeg + 32; ++r) {
            const float* row = &sX[r * 33];
            float b0 = row[j4 * 4], b1 = row[j4 * 4 + 1];
            float b2 = row[j4 * 4 + 2], b3 = row[j4 * 4 + 3];
            ull bp0 = pk2(b0, b1), bp1 = pk2(b2, b3);
#pragma unroll
            for (int ii = 0; ii < 4; ++ii) {
                float a = row[i4 * 4 + ii];
                ull ap = pk2(a, a);
                acc[ii][0] = fma2(ap, bp0, acc[ii][0]);
                acc[ii][1] = fma2(ap, bp1, acc[ii][1]);
            }
        }
        if (tid < 128) {
            int c = tid & 31, rg = tid >> 5;
#pragma unroll 8
            for (int r = rg * 32; r < rg * 32 + 32; ++r) musum += sX[r * 33 + c];
        }
    }
#pragma unroll
    for (int ii = 0; ii < 4; ++ii) {
        float v0, v1, v2, v3;
        upk2(acc[ii][0], v0, v1);
        upk2(acc[ii][1], v2, v3);
        int rowc = (i4 * 4 + ii) * 32 + j4 * 4;
        atomicAdd(&sCov[rowc], v0);
        atomicAdd(&sCov[rowc + 1], v1);
        atomicAdd(&sCov[rowc + 2], v2);
        atomicAdd(&sCov[rowc + 3], v3);
    }
    if (tid < 128) atomicAdd(&sMu[tid & 31], musum);
    __syncthreads();
    for (int t = tid; t < 1024; t += 256) atomicAdd(&g_cov[t], sCov[t]);
    if (tid < 32) atomicAdd(&g_mu[tid], sMu[tid]);   // exact: each row counted once
}

// ---- finalize bn1 from covariance -----------------------------------------
__global__ __launch_bounds__(64) void k_fin1(const float* __restrict__ W1,
                                             const float* __restrict__ b1,
                                             const float* __restrict__ g1,
                                             const float* __restrict__ be1,
                                             float invV) {
    __shared__ float sS[1024];
    __shared__ float sMu[32];
    int tid = threadIdx.x;
    for (int t = tid; t < 1024; t += 64) sS[t] = g_cov[t];
    if (tid < 32) sMu[tid] = g_mu[tid];
    __syncthreads();
    float w[32];
#pragma unroll
    for (int s = 0; s < 32; ++s) w[s] = W1[s * 64 + tid];
    float wmu = 0.f;
#pragma unroll
    for (int s = 0; s < 32; ++s) wmu = fmaf(w[s], sMu[s], wmu);
    float quad = 0.f;
#pragma unroll 4
    for (int s = 0; s < 32; ++s) {
        float acc = 0.f;
#pragma unroll
        for (int t = 0; t < 32; ++t) acc = fmaf(sS[s * 32 + t], w[t], acc);
        quad = fmaf(w[s], acc, quad);
    }
    float m = wmu * invV;
    float var = quad * invV - m * m;
    float mean = m + b1[tid];
    float sc = g1[tid] / sqrtf(var + 1e-5f);
    g_bn1[tid] = sc;
    g_bn1[64 + tid] = be1[tid] - mean * sc;
}

__global__ void k_finalize2(const float* __restrict__ gg,
                            const float* __restrict__ bb, float invV) {
    int c = threadIdx.x;
    if (c >= 64) return;
    float mean = g_stats[128 + c] * invV;
    float var  = g_stats[192 + c] * invV - mean * mean;
    float sc = gg[c] / sqrtf(var + 1e-5f);
    g_bn2[c] = sc;
    g_bn2[64 + c] = bb[c] - mean * sc;
}

// ---- fused: x_proj -> Y1 -> bn1/relu -> @W2 -> Y2 (+stats2) ---------------
// dynamic smem layout (floats):
//  [0..8319]      sX (stage1 LD33, uses 0..4223) / sX2 (stage2 LD65)
//  [4224..6527]   sW1T [c*36+k]  (stage1 only)
//  [8320..12671]  sW2T [c*68+k]  (persistent)
#define F12_SMEM_FLOATS 12672
__global__ __launch_bounds__(128) void k_fused12(const float* __restrict__ xproj,
                                                 const float* __restrict__ b1,
                                                 const float* __restrict__ W1,
                                                 const float* __restrict__ W2,
                                                 const float* __restrict__ b2, int V) {
    extern __shared__ float sm[];
    float* sX   = sm;
    float* sW1T = sm + 4224;
    float* sX2  = sm;
    float* sW2T = sm + 8320;
    int tid = threadIdx.x;
    int row0 = blockIdx.x * 128;

    load_rm<32, 33, 128>(xproj, row0, V, 32, 0, sX, tid);
    for (int t = tid; t < 2048; t += 128) {
        int k = t & 31, c = t >> 5;
        sW1T[c * 36 + k] = W1[k * 64 + c];
    }
    for (int t = tid; t < 4096; t += 128) {
        int k = t & 63, c = t >> 6;
        sW2T[c * 68 + k] = W2[k * 64 + c];
    }
    __syncthreads();

    int tx = tid & 7, ty = tid >> 3;
    int r0 = ty * 8;

    ull acc[8][4] = {};
#pragma unroll 2
    for (int k4 = 0; k4 < 8; ++k4)
        mm_chunk<33, 36>(sX, sW1T, acc, tx, r0, k4);

    // bn1 + relu -> h[r][j], col of j is tx+8j; pair p = (j=2p, j=2p+1)
    float h[8][8];
#pragma unroll
    for (int p = 0; p < 4; ++p) {
        int cA = tx + 16 * p, cB = cA + 8;
        float bA = b1[cA], bB = b1[cB];
        float sA = g_bn1[cA], sB = g_bn1[cB];
        float hA = g_bn1[64 + cA], hB = g_bn1[64 + cB];
#pragma unroll
        for (int r = 0; r < 8; ++r) {
            float yA, yB;
            upk2(acc[r][p], yA, yB);
            h[r][2 * p]     = fmaxf(fmaf(yA + bA, sA, hA), 0.f);
            h[r][2 * p + 1] = fmaxf(fmaf(yB + bB, sB, hB), 0.f);
        }
    }
    __syncthreads();   // sX/sW1T dead

    // h -> sX2[(r)(LD65) + c], conflict-free scalar stores
#pragma unroll
    for (int r = 0; r < 8; ++r)
#pragma unroll
        for (int j = 0; j < 8; ++j)
            sX2[(r0 + r) * 65 + tx + 8 * j] = h[r][j];
    __syncthreads();

    ull acc2[8][4] = {};
#pragma unroll 2
    for (int k4 = 0; k4 < 16; ++k4)
        mm_chunk<65, 68>(sX2, sW2T, acc2, tx, r0, k4);
    __syncthreads();   // sX2 dead -> stats scratch

    float s[8] = {}, q[8] = {};
#pragma unroll
    for (int p = 0; p < 4; ++p) {
        int cA = tx + 16 * p, cB = cA + 8;
        float bA = b2[cA], bB = b2[cB];
#pragma unroll
        for (int r = 0; r < 8; ++r) {
            int row = row0 + r0 + r;
            float yA, yB;
            upk2(acc2[r][p], yA, yB);
            yA += bA; yB += bB;
            if (row < V) {
                g_Y2[(size_t)row * 64 + cA] = yA;
                g_Y2[(size_t)row * 64 + cB] = yB;
                s[2 * p] += yA;     q[2 * p] += yA * yA;
                s[2 * p + 1] += yB; q[2 * p + 1] += yB * yB;
            }
        }
    }
    // reduce over ty within warp (lane = ty*8+tx; xor 8/16 collapse ty)
    int lane = tid & 31, wrp = tid >> 5;
#pragma unroll
    for (int j = 0; j < 8; ++j) {
        s[j] += __shfl_xor_sync(0xffffffffu, s[j], 8);
        s[j] += __shfl_xor_sync(0xffffffffu, s[j], 16);
        q[j] += __shfl_xor_sync(0xffffffffu, q[j], 8);
        q[j] += __shfl_xor_sync(0xffffffffu, q[j], 16);
    }
    float* sPart = sm;   // 4 warps * 128
    if (lane < 8) {
#pragma unroll
        for (int j = 0; j < 8; ++j) {
            int c = lane + 8 * j;          // lane==tx here
            sPart[wrp * 128 + c] = s[j];
            sPart[wrp * 128 + 64 + c] = q[j];
        }
    }
    __syncthreads();
    if (tid < 128) {
        float t = 0.f;
#pragma unroll
        for (int w = 0; w < 4; ++w) t += sPart[w * 128 + tid];
        atomicAdd(&g_stats[128 + tid], t);   // [128..191]=sum, [192..255]=sq
    }
}

// ---- R = x_main @ Acmb + r0  (col tiles of 64, K split 2x32) --------------
__global__ __launch_bounds__(128) void k_R(const float* __restrict__ xmain, int N) {
    __shared__ __align__(16) float sX[128 * 33];
    __shared__ __align__(16) float sWT[2 * 64 * 36];
    int tid = threadIdx.x;
    int row0 = blockIdx.x * 128;
    int jt = blockIdx.y;
    for (int t = tid; t < 4096; t += 128) {
        int k = t & 63, c = t >> 6;                 // global k 0..63
        sWT[(k >> 5) * 2304 + c * 36 + (k & 31)] = g_Acmb[k * 192 + jt * 64 + c];
    }
    int tx = tid & 7, ty = tid >> 3;
    int r0 = ty * 8;
    ull acc[8][4] = {};

    load_rm<32, 33, 128>(xmain, row0, N, 64, 0, sX, tid);
    __syncthreads();
#pragma unroll 2
    for (int k4 = 0; k4 < 8; ++k4)
        mm_chunk<33, 36>(sX, sWT, acc, tx, r0, k4);
    __syncthreads();
    load_rm<32, 33, 128>(xmain, row0, N, 64, 32, sX, tid);
    __syncthreads();
#pragma unroll 2
    for (int k4 = 0; k4 < 8; ++k4)
        mm_chunk<33, 36>(sX, sWT + 2304, acc, tx, r0, k4);

#pragma unroll
    for (int p = 0; p < 4; ++p) {
        int cA = tx + 16 * p, cB = cA + 8;
        float bA = g_r0[jt * 64 + cA], bB = g_r0[jt * 64 + cB];
#pragma unroll
        for (int r = 0; r < 8; ++r) {
            int row = row0 + r0 + r;
            if (row < N) {
                float yA, yB;
                upk2(acc[r][p], yA, yB);
                g_R[(size_t)row * 192 + jt * 64 + cA] = yA + bA;
                g_R[(size_t)row * 192 + jt * 64 + cB] = yB + bB;
            }
        }
    }
}

// ---- c_n = bk . q_n -------------------------------------------------------
__global__ __launch_bounds__(256) void k_c(const float* __restrict__ xmain, int N) {
    int w = (blockIdx.x * blockDim.x + threadIdx.x) >> 5;
    int l = threadIdx.x & 31;
    if (w >= N) return;
    float p = xmain[(size_t)w * 64 + l] * g_wc[l]
            + xmain[(size_t)w * 64 + 32 + l] * g_wc[32 + l];
#pragma unroll
    for (int o = 16; o; o >>= 1) p += __shfl_xor_sync(0xffffffffu, p, o);
    if (l == 0) g_c[w] = p + g_c0[0];
}

// ---- X_v = h2_v . R_seg[0:64] + xmod_v . R_seg[64:192] + c_seg ------------
__global__ __launch_bounds__(256) void k_score(const float* __restrict__ xmod, int V) {
    int w = (blockIdx.x * blockDim.x + threadIdx.x) >> 5;
    int l = threadIdx.x & 31;
    if (w >= V) return;
    int sg = g_seg[w];
    const float* R = g_R + (size_t)sg * 192;
    float p = 0.f;
#pragma unroll
    for (int j = 0; j < 2; ++j) {
        int c = l + 32 * j;
        float y = g_Y2[(size_t)w * 64 + c];
        float h = fmaxf(fmaf(y, g_bn2[c], g_bn2[64 + c]), 0.f);
        p = fmaf(h, __ldg(&R[c]), p);
    }
#pragma unroll
    for (int j = 0; j < 4; ++j) {
        int c = l + 32 * j;
        p = fmaf(xmod[(size_t)w * 128 + c], __ldg(&R[64 + c]), p);
    }
#pragma unroll
    for (int o = 16; o; o >>= 1) p += __shfl_xor_sync(0xffffffffu, p, o);
    if (l == 0) g_X[w] = p + g_c[sg];
}

// ---- per-segment scaled softmax + weighted max-pool + gate ----------------
__global__ __launch_bounds__(256) void k_pool(const int* __restrict__ csr,
                                              const float* __restrict__ xmod,
                                              float* __restrict__ out,
                                              int N, int hasSeen) {
    int warp = (blockIdx.x * blockDim.x + threadIdx.x) >> 5;
    int lane = threadIdx.x & 31;
    if (warp >= N) return;
    int s = csr[warp], e = csr[warp + 1];
    int cnt = e - s;
    float* orow = out + (size_t)warp * 128;
    if (cnt <= 0) {
        orow[lane] = 0.f; orow[lane + 32] = 0.f;
        orow[lane + 64] = 0.f; orow[lane + 96] = 0.f;
        if (hasSeen && lane == 0) out[(size_t)N * 128 + warp] = 0.f;
        return;
    }
    const float NEG_INF = __int_as_float(0xff800000);
    float m = NEG_INF;
    for (int v = s + lane; v < e; v += 32) m = fmaxf(m, g_X[v]);
#pragma unroll
    for (int o = 16; o; o >>= 1) m = fmaxf(m, __shfl_xor_sync(0xffffffffu, m, o));
    float inv = rsqrtf((float)cnt);
    float ss = 0.f;
    for (int v = s + lane; v < e; v += 32) ss += expf((g_X[v] - m) * inv);
#pragma unroll
    for (int o = 16; o; o >>= 1) ss += __shfl_xor_sync(0xffffffffu, ss, o);
    float rden = 1.0f / (ss + 1e-12f);
    float G = tanhf(fmaxf(m, 0.f));
    float p0 = NEG_INF, p1 = NEG_INF, p2 = NEG_INF, p3 = NEG_INF;
    int v = s;
    for (; v + 1 < e; v += 2) {
        float a0 = expf((g_X[v] - m) * inv) * rden;
        float a1 = expf((g_X[v + 1] - m) * inv) * rden;
        const float* x0 = xmod + (size_t)v * 128;
        const float* x1 = x0 + 128;
        float u0 = x0[lane], u1 = x0[lane + 32], u2 = x0[lane + 64], u3 = x0[lane + 96];
        float w0 = x1[lane], w1 = x1[lane + 32], w2 = x1[lane + 64], w3 = x1[lane + 96];
        p0 = fmaxf(p0, fmaxf(u0 * a0, w0 * a1));
        p1 = fmaxf(p1, fmaxf(u1 * a0, w1 * a1));
        p2 = fmaxf(p2, fmaxf(u2 * a0, w2 * a1));
        p3 = fmaxf(p3, fmaxf(u3 * a0, w3 * a1));
    }
    if (v < e) {
        float a = expf((g_X[v] - m) * inv) * rden;
        const float* xr = xmod + (size_t)v * 128;
        p0 = fmaxf(p0, xr[lane] * a);
        p1 = fmaxf(p1, xr[lane + 32] * a);
        p2 = fmaxf(p2, xr[lane + 64] * a);
        p3 = fmaxf(p3, xr[lane + 96] * a);
    }
    orow[lane]      = p0 * G;
    orow[lane + 32] = p1 * G;
    orow[lane + 64] = p2 * G;
    orow[lane + 96] = p3 * G;
    if (hasSeen && lane == 0) out[(size_t)N * 128 + warp] = 1.f;
}

// ---------------------------------------------------------------------------
extern "C" void kernel_launch(void* const* d_in, const int* in_sizes, int n_in,
                              void* d_out, int out_size) {
    const float* x_main = (const float*)d_in[0];
    const float* x_mod  = (const float*)d_in[1];
    const float* x_proj = (const float*)d_in[2];
    const int*   csr    = (const int*)d_in[3];
    const float* Wq = (const float*)d_in[4];
    const float* bq = (const float*)d_in[5];
    const float* W1 = (const float*)d_in[6];
    const float* b1 = (const float*)d_in[7];
    const float* g1 = (const float*)d_in[8];
    const float* be1 = (const float*)d_in[9];
    const float* W2 = (const float*)d_in[10];
    const float* b2 = (const float*)d_in[11];
    const float* g2 = (const float*)d_in[12];
    const float* be2 = (const float*)d_in[13];
    const float* Wk = (const float*)d_in[14];
    const float* bk = (const float*)d_in[15];

    int N = in_sizes[0] / 64;
    int V = in_sizes[1] / 128;
    float* out = (float*)d_out;
    int hasSeen = (out_size >= N * 129) ? 1 : 0;
    float invV = 1.0f / (float)V;

    int vb128 = (V + 127) / 128;
    int nb128 = (N + 127) / 128;

    static int attrDone = 0;
    if (!attrDone) {
        cudaFuncSetAttribute(k_fused12, cudaFuncAttributeMaxDynamicSharedMemorySize,
                             F12_SMEM_FLOATS * 4);
        attrDone = 1;
    }

    k_zero<<<4, 256>>>();
    k_seg<<<(N + 255) / 256, 256>>>(csr, N);
    k_prep<<<1, 256>>>(Wq, bq, Wk, bk);
    k_cov<<<(V + 511) / 512, 256>>>(x_proj, V);
    k_fin1<<<1, 64>>>(W1, b1, g1, be1, invV);
    k_fused12<<<vb128, 128, F12_SMEM_FLOATS * 4>>>(x_proj, b1, W1, W2, b2, V);
    k_finalize2<<<1, 64>>>(g2, be2, invV);
    {
        dim3 g(nb128, 3);
        k_R<<<g, 128>>>(x_main, N);
    }
    k_c<<<(N * 32 + 255) / 256, 256>>>(x_main, N);
    k_score<<<(V * 32 + 255) / 256, 256>>>(x_mod, V);
    k_pool<<<(N * 32 + 255) / 256, 256>>>(csr, x_mod, out, N, hasSeen);
}

// round 8
// speedup vs baseline: 1.3118x; 1.3118x over previous
#include <cuda_runtime.h>
#include <math.h>

// ---------------------------------------------------------------------------
// AttentiveBimodalCSRPool — round 7 (consolidation).
//   R3 GEMM kernels (proven 947us) + validated covariance BN1 path (R5)
//   replacing the full stage-1 stats GEMM. Unrolled pool from R5.
// ---------------------------------------------------------------------------

#define MAXV 1000000
#define MAXN 125056
typedef unsigned long long ull;

__device__ float g_Y2[(size_t)MAXV * 64];
__device__ float g_R[(size_t)MAXN * 192];
__device__ float g_c[MAXN];
__device__ float g_X[MAXV];
__device__ int   g_seg[MAXV];
__device__ float g_stats[256];    // [128..191]=sum2, [192..255]=sq2
__device__ float g_cov[32 * 32];
__device__ float g_mu[32];
__device__ float g_bn1[128];      // [scale(64), shift(64)]
__device__ float g_bn2[128];
__device__ float g_Acmb[64 * 192];
__device__ float g_r0[192];
__device__ float g_wc[64];
__device__ float g_c0[1];

// ---- packed f32x2 helpers -------------------------------------------------
__device__ __forceinline__ ull pk2(float lo, float hi) {
    ull r; asm("mov.b64 %0, {%1, %2};" : "=l"(r) : "f"(lo), "f"(hi)); return r;
}
__device__ __forceinline__ ull fma2(ull a, ull b, ull c) {
    ull d; asm("fma.rn.f32x2 %0, %1, %2, %3;" : "=l"(d) : "l"(a), "l"(b), "l"(c));
    return d;
}
__device__ __forceinline__ void upk2(ull v, float& lo, float& hi) {
    asm("mov.b64 {%0, %1}, %2;" : "=f"(lo), "=f"(hi) : "l"(v));
}

// ---- row-major tile loader: sX[r][k], LD odd => conflict-free -------------
template <int K, int LD, int NT>
__device__ __forceinline__ void load_rm(const float* __restrict__ src,
                                        int row0, int limit,
                                        int srcStride, int srcOff,
                                        float* __restrict__ sX, int tid) {
    constexpr int K4 = K / 4;
    for (int t = tid; t < 128 * K4; t += NT) {
        int c4 = t % K4;
        int r  = t / K4;
        int row = row0 + r;
        float4 x = make_float4(0.f, 0.f, 0.f, 0.f);
        if (row < limit)
            x = *reinterpret_cast<const float4*>(&src[(size_t)row * srcStride + srcOff + c4 * 4]);
        float* d = &sX[r * LD + c4 * 4];
        d[0] = x.x; d[1] = x.y; d[2] = x.z; d[3] = x.w;
    }
}

// ---- 128x64 tile micro-kernel, A row-major sX[r*LD+k] ---------------------
// 128 threads: tx=tid&7 -> cols tx*8..+7 ; ty=tid>>3 -> rows ty*8..+7.
template <int K, int LD>
__device__ __forceinline__ void mm8_rm(const float* __restrict__ sX,
                                       const float* __restrict__ sW,  // [K][64]
                                       ull acc[8][4], int tx, int ty) {
    const int c0 = tx * 8, r0 = ty * 8;
#pragma unroll 8
    for (int k = 0; k < K; ++k) {
        ulonglong2 w0 = *reinterpret_cast<const ulonglong2*>(&sW[k * 64 + c0]);
        ulonglong2 w1 = *reinterpret_cast<const ulonglong2*>(&sW[k * 64 + c0 + 4]);
#pragma unroll
        for (int i = 0; i < 8; ++i) {
            float a = sX[(r0 + i) * LD + k];
            ull ap = pk2(a, a);
            acc[i][0] = fma2(ap, w0.x, acc[i][0]);
            acc[i][1] = fma2(ap, w0.y, acc[i][1]);
            acc[i][2] = fma2(ap, w1.x, acc[i][2]);
            acc[i][3] = fma2(ap, w1.y, acc[i][3]);
        }
    }
}

// ---- same but A transposed: sXT[k*128 + r] (for h1T) ----------------------
template <int K>
__device__ __forceinline__ void mm8_cm(const float* __restrict__ sXT,
                                       const float* __restrict__ sW,
                                       ull acc[8][4], int tx, int ty) {
    const int c0 = tx * 8, r0 = ty * 8;
#pragma unroll 8
    for (int k = 0; k < K; ++k) {
        ulonglong2 w0 = *reinterpret_cast<const ulonglong2*>(&sW[k * 64 + c0]);
        ulonglong2 w1 = *reinterpret_cast<const ulonglong2*>(&sW[k * 64 + c0 + 4]);
#pragma unroll
        for (int i = 0; i < 8; ++i) {
            float a = sXT[k * 128 + r0 + i];
            ull ap = pk2(a, a);
            acc[i][0] = fma2(ap, w0.x, acc[i][0]);
            acc[i][1] = fma2(ap, w0.y, acc[i][1]);
            acc[i][2] = fma2(ap, w1.x, acc[i][2]);
            acc[i][3] = fma2(ap, w1.y, acc[i][3]);
        }
    }
}

// ---- block stats reduction for 128-thread / 8-col-per-thread layout -------
__device__ __forceinline__ void stats_reduce8(float s[8], float q[8], int tid,
                                              float* sPart /*4*128*/,
                                              float* gsum, float* gsq) {
    int lane = tid & 31, wrp = tid >> 5;
#pragma unroll
    for (int j = 0; j < 8; ++j) {
        s[j] += __shfl_xor_sync(0xffffffffu, s[j], 8);
        s[j] += __shfl_xor_sync(0xffffffffu, s[j], 16);
        q[j] += __shfl_xor_sync(0xffffffffu, q[j], 8);
        q[j] += __shfl_xor_sync(0xffffffffu, q[j], 16);
    }
    if (lane < 8) {
        int c0 = lane * 8;
#pragma unroll
        for (int j = 0; j < 8; ++j) {
            sPart[wrp * 128 + c0 + j] = s[j];
            sPart[wrp * 128 + 64 + c0 + j] = q[j];
        }
    }
    __syncthreads();
    if (tid < 128) {
        float t = 0.f;
#pragma unroll
        for (int w = 0; w < 4; ++w) t += sPart[w * 128 + tid];
        if (tid < 64) atomicAdd(gsum + tid, t);
        else          atomicAdd(gsq + (tid - 64), t);
    }
}

// ---------------------------------------------------------------------------
__global__ void k_zero() {
    int t = threadIdx.x + blockIdx.x * blockDim.x;
    if (t < 128) g_stats[128 + t] = 0.f;
    if (t < 1024) g_cov[t] = 0.f;
    if (t < 32) g_mu[t] = 0.f;
}

__global__ void k_seg(const int* __restrict__ csr, int N) {
    int n = blockIdx.x * blockDim.x + threadIdx.x;
    if (n < N) {
        int s = csr[n], e = csr[n + 1];
        for (int v = s; v < e; ++v) g_seg[v] = n;
    }
}

// ---- combined weights (smem-tiled): Acmb = Wq@Wk^T, r0, wc, c0 ------------
__global__ __launch_bounds__(256) void k_prep(const float* __restrict__ Wq,
                                              const float* __restrict__ bq,
                                              const float* __restrict__ Wk,
                                              const float* __restrict__ bk) {
    __shared__ float sWq[64 * 64];
    __shared__ float sWk[64 * 65];
    __shared__ float sbq[64], sbk[64];
    int tid = threadIdx.x;
    for (int i = tid; i < 64 * 64; i += 256) sWq[i] = Wq[i];
    if (tid < 64) { sbq[tid] = bq[tid]; sbk[tid] = bk[tid]; }
    __syncthreads();
    int irow = tid >> 6;
    int jl   = tid & 63;
    for (int cc = 0; cc < 3; ++cc) {
        __syncthreads();
        for (int t = tid; t < 64 * 64; t += 256) {
            int jj = t >> 6, s = t & 63;
            sWk[jj * 65 + s] = Wk[(cc * 64 + jj) * 64 + s];
        }
        __syncthreads();
#pragma unroll 4
        for (int it = 0; it < 16; ++it) {
            int ii = it * 4 + irow;
            float a = 0.f;
#pragma unroll 8
            for (int s = 0; s < 64; ++s)
                a = fmaf(sWq[ii * 64 + s], sWk[jl * 65 + s], a);
            g_Acmb[ii * 192 + cc * 64 + jl] = a;
        }
        if (tid < 64) {
            float a = 0.f;
#pragma unroll 8
            for (int s = 0; s < 64; ++s) a = fmaf(sbq[s], sWk[tid * 65 + s], a);
            g_r0[cc * 64 + tid] = a;
        }
    }
    if (tid < 64) {
        float a = 0.f;
#pragma unroll 8
        for (int s = 0; s < 64; ++s) a = fmaf(sWq[tid * 64 + s], sbk[s], a);
        g_wc[tid] = a;
    }
    if (tid == 0) {
        float a = 0.f;
        for (int s = 0; s < 64; ++s) a = fmaf(sbq[s], sbk[s], a);
        g_c0[0] = a;
    }
}

// ---- SYRK: g_cov += x_proj^T x_proj, g_mu += colsum (validated R5) --------
__global__ __launch_bounds__(256) void k_cov(const float* __restrict__ xproj, int V) {
    __shared__ __align__(16) float sX[128 * 33];
    __shared__ float sCov[1024];
    __shared__ float sMu[32];
    int tid = threadIdx.x;
    for (int t = tid; t < 1024; t += 256) sCov[t] = 0.f;
    if (tid < 32) sMu[tid] = 0.f;

    int i4 = tid & 7;
    int j4 = (tid >> 3) & 7;
    int rs = tid >> 6;
    ull acc[4][2] = {};
    float musum = 0.f;
    int base = blockIdx.x * 512;

    for (int tile = 0; tile < 4; ++tile) {
        __syncthreads();
        load_rm<32, 33, 256>(xproj, base + tile * 128, V, 32, 0, sX, tid);
        __syncthreads();
        int rbeg = rs * 32;
#pragma unroll 4
        for (int r = rbeg; r < rbeg + 32; ++r) {
            const float* row = &sX[r * 33];
            float b0 = row[j4 * 4], b1 = row[j4 * 4 + 1];
            float b2 = row[j4 * 4 + 2], b3 = row[j4 * 4 + 3];
            ull bp0 = pk2(b0, b1), bp1 = pk2(b2, b3);
#pragma unroll
            for (int ii = 0; ii < 4; ++ii) {
                float a = row[i4 * 4 + ii];
                ull ap = pk2(a, a);
                acc[ii][0] = fma2(ap, bp0, acc[ii][0]);
                acc[ii][1] = fma2(ap, bp1, acc[ii][1]);
            }
        }
        if (tid < 128) {
            int c = tid & 31, rg = tid >> 5;
#pragma unroll 8
            for (int r = rg * 32; r < rg * 32 + 32; ++r) musum += sX[r * 33 + c];
        }
    }
#pragma unroll
    for (int ii = 0; ii < 4; ++ii) {
        float v0, v1, v2, v3;
        upk2(acc[ii][0], v0, v1);
        upk2(acc[ii][1], v2, v3);
        int rowc = (i4 * 4 + ii) * 32 + j4 * 4;
        atomicAdd(&sCov[rowc], v0);
        atomicAdd(&sCov[rowc + 1], v1);
        atomicAdd(&sCov[rowc + 2], v2);
        atomicAdd(&sCov[rowc + 3], v3);
    }
    if (tid < 128) atomicAdd(&sMu[tid & 31], musum);
    __syncthreads();
    for (int t = tid; t < 1024; t += 256) atomicAdd(&g_cov[t], sCov[t]);
    if (tid < 32) atomicAdd(&g_mu[tid], sMu[tid]);
}

// ---- finalize bn1 from covariance -----------------------------------------
__global__ __launch_bounds__(64) void k_fin1(const float* __restrict__ W1,
                                             const float* __restrict__ b1,
                                             const float* __restrict__ g1,
                                             const float* __restrict__ be1,
                                             float invV) {
    __shared__ float sS[1024];
    __shared__ float sMu[32];
    int tid = threadIdx.x;
    for (int t = tid; t < 1024; t += 64) sS[t] = g_cov[t];
    if (tid < 32) sMu[tid] = g_mu[tid];
    __syncthreads();
    float w[32];
#pragma unroll
    for (int s = 0; s < 32; ++s) w[s] = W1[s * 64 + tid];
    float wmu = 0.f;
#pragma unroll
    for (int s = 0; s < 32; ++s) wmu = fmaf(w[s], sMu[s], wmu);
    float quad = 0.f;
#pragma unroll 4
    for (int s = 0; s < 32; ++s) {
        float acc = 0.f;
#pragma unroll
        for (int t = 0; t < 32; ++t) acc = fmaf(sS[s * 32 + t], w[t], acc);
        quad = fmaf(w[s], acc, quad);
    }
    float m = wmu * invV;
    float var = quad * invV - m * m;
    float mean = m + b1[tid];
    float sc = g1[tid] / sqrtf(var + 1e-5f);
    g_bn1[tid] = sc;
    g_bn1[64 + tid] = be1[tid] - mean * sc;
}

__global__ void k_finalize2(const float* __restrict__ gg,
                            const float* __restrict__ bb, float invV) {
    int c = threadIdx.x;
    if (c >= 64) return;
    float mean = g_stats[128 + c] * invV;
    float var  = g_stats[192 + c] * invV - mean * mean;
    float sc = gg[c] / sqrtf(var + 1e-5f);
    g_bn2[c] = sc;
    g_bn2[64 + c] = bb[c] - mean * sc;
}

// ---- fused: x_proj -> Y1 -> bn1/relu -> @W2 -> Y2 (+stats2)  [R3 proven] --
__global__ __launch_bounds__(128) void k_fused12(const float* __restrict__ xproj,
                                                 const float* __restrict__ b1,
                                                 const float* __restrict__ W1,
                                                 const float* __restrict__ W2,
                                                 const float* __restrict__ b2, int V) {
    __shared__ __align__(16) float smA[64 * 128];
    __shared__ __align__(16) float sW2[64 * 64];
    float* sX  = smA;
    float* sW1 = smA + 128 * 33;
    float* h1T = smA;
    int tid = threadIdx.x;
    int row0 = blockIdx.x * 128;

    load_rm<32, 33, 128>(xproj, row0, V, 32, 0, sX, tid);
    for (int i = tid; i < 32 * 64; i += 128) sW1[i] = W1[i];
    for (int i = tid; i < 64 * 64; i += 128) sW2[i] = W2[i];
    __syncthreads();

    int tx = tid & 7, ty = tid >> 3;
    int c0 = tx * 8, r0 = ty * 8;
    ull acc[8][4] = {};
    mm8_rm<32, 33>(sX, sW1, acc, tx, ty);

    float bb[8], sc[8], sh[8];
#pragma unroll
    for (int j = 0; j < 8; ++j) {
        bb[j] = b1[c0 + j];
        sc[j] = g_bn1[c0 + j];
        sh[j] = g_bn1[64 + c0 + j];
    }
    float h[8][8];
#pragma unroll
    for (int i = 0; i < 8; ++i) {
#pragma unroll
        for (int jp = 0; jp < 4; ++jp) {
            float y0, y1;
            upk2(acc[i][jp], y0, y1);
            h[i][jp * 2]     = fmaxf(fmaf(y0 + bb[jp * 2],     sc[jp * 2],     sh[jp * 2]),     0.f);
            h[i][jp * 2 + 1] = fmaxf(fmaf(y1 + bb[jp * 2 + 1], sc[jp * 2 + 1], sh[jp * 2 + 1]), 0.f);
        }
    }
    __syncthreads();

#pragma unroll
    for (int j = 0; j < 8; ++j) {
        *reinterpret_cast<float4*>(&h1T[(c0 + j) * 128 + r0]) =
            make_float4(h[0][j], h[1][j], h[2][j], h[3][j]);
        *reinterpret_cast<float4*>(&h1T[(c0 + j) * 128 + r0 + 4]) =
            make_float4(h[4][j], h[5][j], h[6][j], h[7][j]);
    }
    __syncthreads();

    ull acc2[8][4] = {};
    mm8_cm<64>(h1T, sW2, acc2, tx, ty);
    __syncthreads();

    float b2v[8];
#pragma unroll
    for (int j = 0; j < 8; ++j) b2v[j] = b2[c0 + j];
    float s[8] = {}, q[8] = {};
#pragma unroll
    for (int i = 0; i < 8; ++i) {
        int row = row0 + r0 + i;
        float y[8];
#pragma unroll
        for (int jp = 0; jp < 4; ++jp) {
            upk2(acc2[i][jp], y[jp * 2], y[jp * 2 + 1]);
            y[jp * 2] += b2v[jp * 2]; y[jp * 2 + 1] += b2v[jp * 2 + 1];
        }
        if (row < V) {
            *reinterpret_cast<float4*>(&g_Y2[(size_t)row * 64 + c0]) =
                make_float4(y[0], y[1], y[2], y[3]);
            *reinterpret_cast<float4*>(&g_Y2[(size_t)row * 64 + c0 + 4]) =
                make_float4(y[4], y[5], y[6], y[7]);
#pragma unroll
            for (int j = 0; j < 8; ++j) { s[j] += y[j]; q[j] += y[j] * y[j]; }
        }
    }
    stats_reduce8(s, q, tid, smA, &g_stats[128], &g_stats[192]);
}

// ---- R = x_main @ Acmb + r0  (col tiles of 64, K split 2x32)  [R3] --------
__global__ __launch_bounds__(128) void k_R(const float* __restrict__ xmain, int N) {
    __shared__ __align__(16) float sX[128 * 33];
    __shared__ __align__(16) float sW[64 * 64];
    int tid = threadIdx.x;
    int row0 = blockIdx.x * 128;
    int jt = blockIdx.y;
    for (int i = tid; i < 64 * 64; i += 128) {
        int k = i >> 6, c = i & 63;
        sW[i] = g_Acmb[k * 192 + jt * 64 + c];
    }
    int tx = tid & 7, ty = tid >> 3;
    int c0 = tx * 8, r0 = ty * 8;
    ull acc[8][4] = {};
    load_rm<32, 33, 128>(xmain, row0, N, 64, 0, sX, tid);
    __syncthreads();
#pragma unroll 8
    for (int k = 0; k < 32; ++k) {
        ulonglong2 w0 = *reinterpret_cast<const ulonglong2*>(&sW[k * 64 + c0]);
        ulonglong2 w1 = *reinterpret_cast<const ulonglong2*>(&sW[k * 64 + c0 + 4]);
#pragma unroll
        for (int i = 0; i < 8; ++i) {
            float a = sX[(r0 + i) * 33 + k];
            ull ap = pk2(a, a);
            acc[i][0] = fma2(ap, w0.x, acc[i][0]);
            acc[i][1] = fma2(ap, w0.y, acc[i][1]);
            acc[i][2] = fma2(ap, w1.x, acc[i][2]);
            acc[i][3] = fma2(ap, w1.y, acc[i][3]);
        }
    }
    __syncthreads();
    load_rm<32, 33, 128>(xmain, row0, N, 64, 32, sX, tid);
    __syncthreads();
#pragma unroll 8
    for (int k = 0; k < 32; ++k) {
        ulonglong2 w0 = *reinterpret_cast<const ulonglong2*>(&sW[(k + 32) * 64 + c0]);
        ulonglong2 w1 = *reinterpret_cast<const ulonglong2*>(&sW[(k + 32) * 64 + c0 + 4]);
#pragma unroll
        for (int i = 0; i < 8; ++i) {
            float a = sX[(r0 + i) * 33 + k];
            ull ap = pk2(a, a);
            acc[i][0] = fma2(ap, w0.x, acc[i][0]);
            acc[i][1] = fma2(ap, w0.y, acc[i][1]);
            acc[i][2] = fma2(ap, w1.x, acc[i][2]);
            acc[i][3] = fma2(ap, w1.y, acc[i][3]);
        }
    }

    float bb[8];
#pragma unroll
    for (int j = 0; j < 8; ++j) bb[j] = g_r0[jt * 64 + c0 + j];
#pragma unroll
    for (int i = 0; i < 8; ++i) {
        int row = row0 + r0 + i;
        if (row < N) {
            float y[8];
#pragma unroll
            for (int jp = 0; jp < 4; ++jp) {
                upk2(acc[i][jp], y[jp * 2], y[jp * 2 + 1]);
                y[jp * 2] += bb[jp * 2]; y[jp * 2 + 1] += bb[jp * 2 + 1];
            }
            *reinterpret_cast<float4*>(&g_R[(size_t)row * 192 + jt * 64 + c0]) =
                make_float4(y[0], y[1], y[2], y[3]);
            *reinterpret_cast<float4*>(&g_R[(size_t)row * 192 + jt * 64 + c0 + 4]) =
                make_float4(y[4], y[5], y[6], y[7]);
        }
    }
}

// ---- c_n = bk . q_n -------------------------------------------------------
__global__ __launch_bounds__(256) void k_c(const float* __restrict__ xmain, int N) {
    int w = (blockIdx.x * blockDim.x + threadIdx.x) >> 5;
    int l = threadIdx.x & 31;
    if (w >= N) return;
    float p = xmain[(size_t)w * 64 + l] * g_wc[l]
            + xmain[(size_t)w * 64 + 32 + l] * g_wc[32 + l];
#pragma unroll
    for (int o = 16; o; o >>= 1) p += __shfl_xor_sync(0xffffffffu, p, o);
    if (l == 0) g_c[w] = p + g_c0[0];
}

// ---- X_v = h2_v . R_seg[0:64] + xmod_v . R_seg[64:192] + c_seg ------------
__global__ __launch_bounds__(256) void k_score(const float* __restrict__ xmod, int V) {
    int w = (blockIdx.x * blockDim.x + threadIdx.x) >> 5;
    int l = threadIdx.x & 31;
    if (w >= V) return;
    int sg = g_seg[w];
    const float* R = g_R + (size_t)sg * 192;
    float p = 0.f;
#pragma unroll
    for (int j = 0; j < 2; ++j) {
        int c = l + 32 * j;
        float y = g_Y2[(size_t)w * 64 + c];
        float h = fmaxf(fmaf(y, g_bn2[c], g_bn2[64 + c]), 0.f);
        p = fmaf(h, __ldg(&R[c]), p);
    }
#pragma unroll
    for (int j = 0; j < 4; ++j) {
        int c = l + 32 * j;
        p = fmaf(xmod[(size_t)w * 128 + c], __ldg(&R[64 + c]), p);
    }
#pragma unroll
    for (int o = 16; o; o >>= 1) p += __shfl_xor_sync(0xffffffffu, p, o);
    if (l == 0) g_X[w] = p + g_c[sg];
}

// ---- per-segment scaled softmax + weighted max-pool + gate ----------------
__global__ __launch_bounds__(256) void k_pool(const int* __restrict__ csr,
                                              const float* __restrict__ xmod,
                                              float* __restrict__ out,
                                              int N, int hasSeen) {
    int warp = (blockIdx.x * blockDim.x + threadIdx.x) >> 5;
    int lane = threadIdx.x & 31;
    if (warp >= N) return;
    int s = csr[warp], e = csr[warp + 1];
    int cnt = e - s;
    float* orow = out + (size_t)warp * 128;
    if (cnt <= 0) {
        orow[lane] = 0.f; orow[lane + 32] = 0.f;
        orow[lane + 64] = 0.f; orow[lane + 96] = 0.f;
        if (hasSeen && lane == 0) out[(size_t)N * 128 + warp] = 0.f;
        return;
    }
    const float NEG_INF = __int_as_float(0xff800000);
    float m = NEG_INF;
    for (int v = s + lane; v < e; v += 32) m = fmaxf(m, g_X[v]);
#pragma unroll
    for (int o = 16; o; o >>= 1) m = fmaxf(m, __shfl_xor_sync(0xffffffffu, m, o));
    float inv = rsqrtf((float)cnt);
    float ss = 0.f;
    for (int v = s + lane; v < e; v += 32) ss += expf((g_X[v] - m) * inv);
#pragma unroll
    for (int o = 16; o; o >>= 1) ss += __shfl_xor_sync(0xffffffffu, ss, o);
    float rden = 1.0f / (ss + 1e-12f);
    float G = tanhf(fmaxf(m, 0.f));
    float p0 = NEG_INF, p1 = NEG_INF, p2 = NEG_INF, p3 = NEG_INF;
    int v = s;
    for (; v + 1 < e; v += 2) {
        float a0 = expf((g_X[v] - m) * inv) * rden;
        float a1 = expf((g_X[v + 1] - m) * inv) * rden;
        const float* x0 = xmod + (size_t)v * 128;
        const float* x1 = x0 + 128;
        float u0 = x0[lane], u1 = x0[lane + 32], u2 = x0[lane + 64], u3 = x0[lane + 96];
        float w0 = x1[lane], w1 = x1[lane + 32], w2 = x1[lane + 64], w3 = x1[lane + 96];
        p0 = fmaxf(p0, fmaxf(u0 * a0, w0 * a1));
        p1 = fmaxf(p1, fmaxf(u1 * a0, w1 * a1));
        p2 = fmaxf(p2, fmaxf(u2 * a0, w2 * a1));
        p3 = fmaxf(p3, fmaxf(u3 * a0, w3 * a1));
    }
    if (v < e) {
        float a = expf((g_X[v] - m) * inv) * rden;
        const float* xr = xmod + (size_t)v * 128;
        p0 = fmaxf(p0, xr[lane] * a);
        p1 = fmaxf(p1, xr[lane + 32] * a);
        p2 = fmaxf(p2, xr[lane + 64] * a);
        p3 = fmaxf(p3, xr[lane + 96] * a);
    }
    orow[lane]      = p0 * G;
    orow[lane + 32] = p1 * G;
    orow[lane + 64] = p2 * G;
    orow[lane + 96] = p3 * G;
    if (hasSeen && lane == 0) out[(size_t)N * 128 + warp] = 1.f;
}

// ---------------------------------------------------------------------------
extern "C" void kernel_launch(void* const* d_in, const int* in_sizes, int n_in,
                              void* d_out, int out_size) {
    const float* x_main = (const float*)d_in[0];
    const float* x_mod  = (const float*)d_in[1];
    const float* x_proj = (const float*)d_in[2];
    const int*   csr    = (const int*)d_in[3];
    const float* Wq = (const float*)d_in[4];
    const float* bq = (const float*)d_in[5];
    const float* W1 = (const float*)d_in[6];
    const float* b1 = (const float*)d_in[7];
    const float* g1 = (const float*)d_in[8];
    const float* be1 = (const float*)d_in[9];
    const float* W2 = (const float*)d_in[10];
    const float* b2 = (const float*)d_in[11];
    const float* g2 = (const float*)d_in[12];
    const float* be2 = (const float*)d_in[13];
    const float* Wk = (const float*)d_in[14];
    const float* bk = (const float*)d_in[15];

    int N = in_sizes[0] / 64;
    int V = in_sizes[1] / 128;
    float* out = (float*)d_out;
    int hasSeen = (out_size >= N * 129) ? 1 : 0;
    float invV = 1.0f / (float)V;

    int vb128 = (V + 127) / 128;
    int nb128 = (N + 127) / 128;

    k_zero<<<4, 256>>>();
    k_seg<<<(N + 255) / 256, 256>>>(csr, N);
    k_prep<<<1, 256>>>(Wq, bq, Wk, bk);
    k_cov<<<(V + 511) / 512, 256>>>(x_proj, V);
    k_fin1<<<1, 64>>>(W1, b1, g1, be1, invV);
    k_fused12<<<vb128, 128>>>(x_proj, b1, W1, W2, b2, V);
    k_finalize2<<<1, 64>>>(g2, be2, invV);
    {
        dim3 g(nb128, 3);
        k_R<<<g, 128>>>(x_main, N);
    }
    k_c<<<(N * 32 + 255) / 256, 256>>>(x_main, N);
    k_score<<<(V * 32 + 255) / 256, 256>>>(x_mod, V);
    k_pool<<<(N * 32 + 255) / 256, 256>>>(csr, x_mod, out, N, hasSeen);
}

// round 10
// speedup vs baseline: 1.3154x; 1.0028x over previous
#include <cuda_runtime.h>
#include <cuda_fp16.h>
#include <math.h>

// ---------------------------------------------------------------------------
// AttentiveBimodalCSRPool — round 9.
//   R7 base (891us) + vectorized k_cov (LDS.128, fused mu) + fp16 Y2
//   (bf16 in R8 failed the 1e-3 gate at 1.02e-3; fp16 has 8x the mantissa).
// ---------------------------------------------------------------------------

#define MAXV 1000000
#define MAXN 125056
typedef unsigned long long ull;

__device__ __align__(16) unsigned short g_Y2h[(size_t)MAXV * 64];  // fp16
__device__ float g_R[(size_t)MAXN * 192];
__device__ float g_c[MAXN];
__device__ float g_X[MAXV];
__device__ int   g_seg[MAXV];
__device__ float g_stats[256];    // [128..191]=sum2, [192..255]=sq2
__device__ float g_cov[32 * 32];
__device__ float g_mu[32];
__device__ float g_bn1[128];      // [scale(64), shift(64)]
__device__ float g_bn2[128];
__device__ float g_Acmb[64 * 192];
__device__ float g_r0[192];
__device__ float g_wc[64];
__device__ float g_c0[1];

// ---- packed f32x2 helpers -------------------------------------------------
__device__ __forceinline__ ull pk2(float lo, float hi) {
    ull r; asm("mov.b64 %0, {%1, %2};" : "=l"(r) : "f"(lo), "f"(hi)); return r;
}
__device__ __forceinline__ ull fma2(ull a, ull b, ull c) {
    ull d; asm("fma.rn.f32x2 %0, %1, %2, %3;" : "=l"(d) : "l"(a), "l"(b), "l"(c));
    return d;
}
__device__ __forceinline__ void upk2(ull v, float& lo, float& hi) {
    asm("mov.b64 {%0, %1}, %2;" : "=f"(lo), "=f"(hi) : "l"(v));
}

// ---- row-major tile loader: sX[r][k], LD odd => conflict-free -------------
template <int K, int LD, int NT>
__device__ __forceinline__ void load_rm(const float* __restrict__ src,
                                        int row0, int limit,
                                        int srcStride, int srcOff,
                                        float* __restrict__ sX, int tid) {
    constexpr int K4 = K / 4;
    for (int t = tid; t < 128 * K4; t += NT) {
        int c4 = t % K4;
        int r  = t / K4;
        int row = row0 + r;
        float4 x = make_float4(0.f, 0.f, 0.f, 0.f);
        if (row < limit)
            x = *reinterpret_cast<const float4*>(&src[(size_t)row * srcStride + srcOff + c4 * 4]);
        float* d = &sX[r * LD + c4 * 4];
        d[0] = x.x; d[1] = x.y; d[2] = x.z; d[3] = x.w;
    }
}

// ---- float4 loader for LD=40 (16B-aligned slots) --------------------------
template <int NT>
__device__ __forceinline__ void load_rm4_40(const float* __restrict__ src,
                                            int row0, int limit,
                                            float* __restrict__ sX, int tid) {
    for (int t = tid; t < 128 * 8; t += NT) {
        int c4 = t & 7;
        int r  = t >> 3;
        int row = row0 + r;
        float4 x = make_float4(0.f, 0.f, 0.f, 0.f);
        if (row < limit)
            x = *reinterpret_cast<const float4*>(&src[(size_t)row * 32 + c4 * 4]);
        *reinterpret_cast<float4*>(&sX[r * 40 + c4 * 4]) = x;
    }
}

// ---- 128x64 tile micro-kernel, A row-major sX[r*LD+k] ---------------------
template <int K, int LD>
__device__ __forceinline__ void mm8_rm(const float* __restrict__ sX,
                                       const float* __restrict__ sW,  // [K][64]
                                       ull acc[8][4], int tx, int ty) {
    const int c0 = tx * 8, r0 = ty * 8;
#pragma unroll 8
    for (int k = 0; k < K; ++k) {
        ulonglong2 w0 = *reinterpret_cast<const ulonglong2*>(&sW[k * 64 + c0]);
        ulonglong2 w1 = *reinterpret_cast<const ulonglong2*>(&sW[k * 64 + c0 + 4]);
#pragma unroll
        for (int i = 0; i < 8; ++i) {
            float a = sX[(r0 + i) * LD + k];
            ull ap = pk2(a, a);
            acc[i][0] = fma2(ap, w0.x, acc[i][0]);
            acc[i][1] = fma2(ap, w0.y, acc[i][1]);
            acc[i][2] = fma2(ap, w1.x, acc[i][2]);
            acc[i][3] = fma2(ap, w1.y, acc[i][3]);
        }
    }
}

// ---- same but A transposed: sXT[k*128 + r] --------------------------------
template <int K>
__device__ __forceinline__ void mm8_cm(const float* __restrict__ sXT,
                                       const float* __restrict__ sW,
                                       ull acc[8][4], int tx, int ty) {
    const int c0 = tx * 8, r0 = ty * 8;
#pragma unroll 8
    for (int k = 0; k < K; ++k) {
        ulonglong2 w0 = *reinterpret_cast<const ulonglong2*>(&sW[k * 64 + c0]);
        ulonglong2 w1 = *reinterpret_cast<const ulonglong2*>(&sW[k * 64 + c0 + 4]);
#pragma unroll
        for (int i = 0; i < 8; ++i) {
            float a = sXT[k * 128 + r0 + i];
            ull ap = pk2(a, a);
            acc[i][0] = fma2(ap, w0.x, acc[i][0]);
            acc[i][1] = fma2(ap, w0.y, acc[i][1]);
            acc[i][2] = fma2(ap, w1.x, acc[i][2]);
            acc[i][3] = fma2(ap, w1.y, acc[i][3]);
        }
    }
}

// ---- block stats reduction (128 thr, 8 cols/thread) -----------------------
__device__ __forceinline__ void stats_reduce8(float s[8], float q[8], int tid,
                                              float* sPart /*4*128*/,
                                              float* gsum, float* gsq) {
    int lane = tid & 31, wrp = tid >> 5;
#pragma unroll
    for (int j = 0; j < 8; ++j) {
        s[j] += __shfl_xor_sync(0xffffffffu, s[j], 8);
        s[j] += __shfl_xor_sync(0xffffffffu, s[j], 16);
        q[j] += __shfl_xor_sync(0xffffffffu, q[j], 8);
        q[j] += __shfl_xor_sync(0xffffffffu, q[j], 16);
    }
    if (lane < 8) {
        int c0 = lane * 8;
#pragma unroll
        for (int j = 0; j < 8; ++j) {
            sPart[wrp * 128 + c0 + j] = s[j];
            sPart[wrp * 128 + 64 + c0 + j] = q[j];
        }
    }
    __syncthreads();
    if (tid < 128) {
        float t = 0.f;
#pragma unroll
        for (int w = 0; w < 4; ++w) t += sPart[w * 128 + tid];
        if (tid < 64) atomicAdd(gsum + tid, t);
        else          atomicAdd(gsq + (tid - 64), t);
    }
}

// ---------------------------------------------------------------------------
// seg expansion + (extra blocks) zero the accumulators
__global__ void k_seg(const int* __restrict__ csr, int N, int segBlocks) {
    if ((int)blockIdx.x >= segBlocks) {
        int t = (blockIdx.x - segBlocks) * blockDim.x + threadIdx.x;
        if (t < 128) g_stats[128 + t] = 0.f;
        if (t < 1024) g_cov[t] = 0.f;
        if (t < 32) g_mu[t] = 0.f;
        return;
    }
    int n = blockIdx.x * blockDim.x + threadIdx.x;
    if (n < N) {
        int s = csr[n], e = csr[n + 1];
        for (int v = s; v < e; ++v) g_seg[v] = n;
    }
}

// ---- combined weights: Acmb = Wq@Wk^T, r0, wc, c0 -------------------------
__global__ __launch_bounds__(256) void k_prep(const float* __restrict__ Wq,
                                              const float* __restrict__ bq,
                                              const float* __restrict__ Wk,
                                              const float* __restrict__ bk) {
    __shared__ float sWq[64 * 64];
    __shared__ float sWk[64 * 65];
    __shared__ float sbq[64], sbk[64];
    int tid = threadIdx.x;
    for (int i = tid; i < 64 * 64; i += 256) sWq[i] = Wq[i];
    if (tid < 64) { sbq[tid] = bq[tid]; sbk[tid] = bk[tid]; }
    __syncthreads();
    int irow = tid >> 6;
    int jl   = tid & 63;
    for (int cc = 0; cc < 3; ++cc) {
        __syncthreads();
        for (int t = tid; t < 64 * 64; t += 256) {
            int jj = t >> 6, s = t & 63;
            sWk[jj * 65 + s] = Wk[(cc * 64 + jj) * 64 + s];
        }
        __syncthreads();
#pragma unroll 4
        for (int it = 0; it < 16; ++it) {
            int ii = it * 4 + irow;
            float a = 0.f;
#pragma unroll 8
            for (int s = 0; s < 64; ++s)
                a = fmaf(sWq[ii * 64 + s], sWk[jl * 65 + s], a);
            g_Acmb[ii * 192 + cc * 64 + jl] = a;
        }
        if (tid < 64) {
            float a = 0.f;
#pragma unroll 8
            for (int s = 0; s < 64; ++s) a = fmaf(sbq[s], sWk[tid * 65 + s], a);
            g_r0[cc * 64 + tid] = a;
        }
    }
    if (tid < 64) {
        float a = 0.f;
#pragma unroll 8
        for (int s = 0; s < 64; ++s) a = fmaf(sWq[tid * 64 + s], sbk[s], a);
        g_wc[tid] = a;
    }
    if (tid == 0) {
        float a = 0.f;
        for (int s = 0; s < 64; ++s) a = fmaf(sbq[s], sbk[s], a);
        g_c0[0] = a;
    }
}

// ---- SYRK via LDS.128: g_cov += x^T x, g_mu += colsum ---------------------
__global__ __launch_bounds__(256) void k_cov(const float* __restrict__ xproj, int V) {
    __shared__ __align__(16) float sX[128 * 40];
    __shared__ float sCov[1024];
    __shared__ float sMu[32];
    int tid = threadIdx.x;
    for (int t = tid; t < 1024; t += 256) sCov[t] = 0.f;
    if (tid < 32) sMu[tid] = 0.f;

    int i4 = tid & 7;
    int j4 = (tid >> 3) & 7;
    int rs = tid >> 6;             // 0..3
    ull acc[4][2] = {};
    float4 msum = make_float4(0.f, 0.f, 0.f, 0.f);
    int base = blockIdx.x * 512;

    for (int tile = 0; tile < 4; ++tile) {
        __syncthreads();
        load_rm4_40<256>(xproj, base + tile * 128, V, sX, tid);
        __syncthreads();
        int rbeg = rs * 32;
#pragma unroll 4
        for (int r = rbeg; r < rbeg + 32; ++r) {
            float4 a = *reinterpret_cast<const float4*>(&sX[r * 40 + i4 * 4]);
            float4 b = *reinterpret_cast<const float4*>(&sX[r * 40 + j4 * 4]);
            ull bp0 = pk2(b.x, b.y), bp1 = pk2(b.z, b.w);
            ull ap;
            ap = pk2(a.x, a.x); acc[0][0] = fma2(ap, bp0, acc[0][0]); acc[0][1] = fma2(ap, bp1, acc[0][1]);
            ap = pk2(a.y, a.y); acc[1][0] = fma2(ap, bp0, acc[1][0]); acc[1][1] = fma2(ap, bp1, acc[1][1]);
            ap = pk2(a.z, a.z); acc[2][0] = fma2(ap, bp0, acc[2][0]); acc[2][1] = fma2(ap, bp1, acc[2][1]);
            ap = pk2(a.w, a.w); acc[3][0] = fma2(ap, bp0, acc[3][0]); acc[3][1] = fma2(ap, bp1, acc[3][1]);
            if (j4 == 0) {
                msum.x += a.x; msum.y += a.y; msum.z += a.z; msum.w += a.w;
            }
        }
    }
#pragma unroll
    for (int ii = 0; ii < 4; ++ii) {
        float v0, v1, v2, v3;
        upk2(acc[ii][0], v0, v1);
        upk2(acc[ii][1], v2, v3);
        int rowc = (i4 * 4 + ii) * 32 + j4 * 4;
        atomicAdd(&sCov[rowc], v0);
        atomicAdd(&sCov[rowc + 1], v1);
        atomicAdd(&sCov[rowc + 2], v2);
        atomicAdd(&sCov[rowc + 3], v3);
    }
    if (j4 == 0) {
        atomicAdd(&sMu[i4 * 4 + 0], msum.x);
        atomicAdd(&sMu[i4 * 4 + 1], msum.y);
        atomicAdd(&sMu[i4 * 4 + 2], msum.z);
        atomicAdd(&sMu[i4 * 4 + 3], msum.w);
    }
    __syncthreads();
    for (int t = tid; t < 1024; t += 256) atomicAdd(&g_cov[t], sCov[t]);
    if (tid < 32) atomicAdd(&g_mu[tid], sMu[tid]);
}

// ---- finalize bn1 from covariance -----------------------------------------
__global__ __launch_bounds__(64) void k_fin1(const float* __restrict__ W1,
                                             const float* __restrict__ b1,
                                             const float* __restrict__ g1,
                                             const float* __restrict__ be1,
                                             float invV) {
    __shared__ float sS[1024];
    __shared__ float sMu[32];
    int tid = threadIdx.x;
    for (int t = tid; t < 1024; t += 64) sS[t] = g_cov[t];
    if (tid < 32) sMu[tid] = g_mu[tid];
    __syncthreads();
    float w[32];
#pragma unroll
    for (int s = 0; s < 32; ++s) w[s] = W1[s * 64 + tid];
    float wmu = 0.f;
#pragma unroll
    for (int s = 0; s < 32; ++s) wmu = fmaf(w[s], sMu[s], wmu);
    float quad = 0.f;
#pragma unroll 4
    for (int s = 0; s < 32; ++s) {
        float acc = 0.f;
#pragma unroll
        for (int t = 0; t < 32; ++t) acc = fmaf(sS[s * 32 + t], w[t], acc);
        quad = fmaf(w[s], acc, quad);
    }
    float m = wmu * invV;
    float var = quad * invV - m * m;
    float mean = m + b1[tid];
    float sc = g1[tid] / sqrtf(var + 1e-5f);
    g_bn1[tid] = sc;
    g_bn1[64 + tid] = be1[tid] - mean * sc;
}

__global__ void k_finalize2(const float* __restrict__ gg,
                            const float* __restrict__ bb, float invV) {
    int c = threadIdx.x;
    if (c >= 64) return;
    float mean = g_stats[128 + c] * invV;
    float var  = g_stats[192 + c] * invV - mean * mean;
    float sc = gg[c] / sqrtf(var + 1e-5f);
    g_bn2[c] = sc;
    g_bn2[64 + c] = bb[c] - mean * sc;
}

// ---- fused: x_proj -> Y1 -> bn1/relu -> @W2 -> Y2(fp16) (+stats2) ---------
__global__ __launch_bounds__(128) void k_fused12(const float* __restrict__ xproj,
                                                 const float* __restrict__ b1,
                                                 const float* __restrict__ W1,
                                                 const float* __restrict__ W2,
                                                 const float* __restrict__ b2, int V) {
    __shared__ __align__(16) float smA[64 * 128];
    __shared__ __align__(16) float sW2[64 * 64];
    float* sX  = smA;
    float* sW1 = smA + 128 * 33;
    float* h1T = smA;
    int tid = threadIdx.x;
    int row0 = blockIdx.x * 128;

    load_rm<32, 33, 128>(xproj, row0, V, 32, 0, sX, tid);
    for (int i = tid; i < 32 * 64; i += 128) sW1[i] = W1[i];
    for (int i = tid; i < 64 * 64; i += 128) sW2[i] = W2[i];
    __syncthreads();

    int tx = tid & 7, ty = tid >> 3;
    int c0 = tx * 8, r0 = ty * 8;
    ull acc[8][4] = {};
    mm8_rm<32, 33>(sX, sW1, acc, tx, ty);

    float bb[8], sc[8], sh[8];
#pragma unroll
    for (int j = 0; j < 8; ++j) {
        bb[j] = b1[c0 + j];
        sc[j] = g_bn1[c0 + j];
        sh[j] = g_bn1[64 + c0 + j];
    }
    float h[8][8];
#pragma unroll
    for (int i = 0; i < 8; ++i) {
#pragma unroll
        for (int jp = 0; jp < 4; ++jp) {
            float y0, y1;
            upk2(acc[i][jp], y0, y1);
            h[i][jp * 2]     = fmaxf(fmaf(y0 + bb[jp * 2],     sc[jp * 2],     sh[jp * 2]),     0.f);
            h[i][jp * 2 + 1] = fmaxf(fmaf(y1 + bb[jp * 2 + 1], sc[jp * 2 + 1], sh[jp * 2 + 1]), 0.f);
        }
    }
    __syncthreads();

#pragma unroll
    for (int j = 0; j < 8; ++j) {
        *reinterpret_cast<float4*>(&h1T[(c0 + j) * 128 + r0]) =
            make_float4(h[0][j], h[1][j], h[2][j], h[3][j]);
        *reinterpret_cast<float4*>(&h1T[(c0 + j) * 128 + r0 + 4]) =
            make_float4(h[4][j], h[5][j], h[6][j], h[7][j]);
    }
    __syncthreads();

    ull acc2[8][4] = {};
    mm8_cm<64>(h1T, sW2, acc2, tx, ty);
    __syncthreads();

    float b2v[8];
#pragma unroll
    for (int j = 0; j < 8; ++j) b2v[j] = b2[c0 + j];
    float s[8] = {}, q[8] = {};
#pragma unroll
    for (int i = 0; i < 8; ++i) {
        int row = row0 + r0 + i;
        float y[8];
#pragma unroll
        for (int jp = 0; jp < 4; ++jp) {
            upk2(acc2[i][jp], y[jp * 2], y[jp * 2 + 1]);
            y[jp * 2] += b2v[jp * 2]; y[jp * 2 + 1] += b2v[jp * 2 + 1];
        }
        if (row < V) {
            union { unsigned short us[8]; uint4 u; } pkv;
#pragma unroll
            for (int j = 0; j < 8; ++j) {
                __half hh = __float2half_rn(y[j]);
                pkv.us[j] = __half_as_ushort(hh);
                float yr = __half2float(hh);      // stats on rounded values
                s[j] += yr; q[j] += yr * yr;
            }
            *reinterpret_cast<uint4*>(&g_Y2h[(size_t)row * 64 + c0]) = pkv.u;
        }
    }
    stats_reduce8(s, q, tid, smA, &g_stats[128], &g_stats[192]);
}

// ---- R = x_main @ Acmb + r0  (col tiles of 64, K split 2x32) --------------
__global__ __launch_bounds__(128) void k_R(const float* __restrict__ xmain, int N) {
    __shared__ __align__(16) float sX[128 * 33];
    __shared__ __align__(16) float sW[64 * 64];
    int tid = threadIdx.x;
    int row0 = blockIdx.x * 128;
    int jt = blockIdx.y;
    for (int i = tid; i < 64 * 64; i += 128) {
        int k = i >> 6, c = i & 63;
        sW[i] = g_Acmb[k * 192 + jt * 64 + c];
    }
    int tx = tid & 7, ty = tid >> 3;
    int c0 = tx * 8, r0 = ty * 8;
    ull acc[8][4] = {};
    load_rm<32, 33, 128>(xmain, row0, N, 64, 0, sX, tid);
    __syncthreads();
    mm8_rm<32, 33>(sX, sW, acc, tx, ty);
    __syncthreads();
    load_rm<32, 33, 128>(xmain, row0, N, 64, 32, sX, tid);
    __syncthreads();
    mm8_rm<32, 33>(sX, sW + 32 * 64, acc, tx, ty);

    float bb[8];
#pragma unroll
    for (int j = 0; j < 8; ++j) bb[j] = g_r0[jt * 64 + c0 + j];
#pragma unroll
    for (int i = 0; i < 8; ++i) {
        int row = row0 + r0 + i;
        if (row < N) {
            float y[8];
#pragma unroll
            for (int jp = 0; jp < 4; ++jp) {
                upk2(acc[i][jp], y[jp * 2], y[jp * 2 + 1]);
                y[jp * 2] += bb[jp * 2]; y[jp * 2 + 1] += bb[jp * 2 + 1];
            }
            *reinterpret_cast<float4*>(&g_R[(size_t)row * 192 + jt * 64 + c0]) =
                make_float4(y[0], y[1], y[2], y[3]);
            *reinterpret_cast<float4*>(&g_R[(size_t)row * 192 + jt * 64 + c0 + 4]) =
                make_float4(y[4], y[5], y[6], y[7]);
        }
    }
}

// ---- c_n = bk . q_n -------------------------------------------------------
__global__ __launch_bounds__(256) void k_c(const float* __restrict__ xmain, int N) {
    int w = (blockIdx.x * blockDim.x + threadIdx.x) >> 5;
    int l = threadIdx.x & 31;
    if (w >= N) return;
    float p = xmain[(size_t)w * 64 + l] * g_wc[l]
            + xmain[(size_t)w * 64 + 32 + l] * g_wc[32 + l];
#pragma unroll
    for (int o = 16; o; o >>= 1) p += __shfl_xor_sync(0xffffffffu, p, o);
    if (l == 0) g_c[w] = p + g_c0[0];
}

// ---- X_v = h2_v . R_seg[0:64] + xmod_v . R_seg[64:192] + c_seg ------------
__global__ __launch_bounds__(256) void k_score(const float* __restrict__ xmod, int V) {
    int w = (blockIdx.x * blockDim.x + threadIdx.x) >> 5;
    int l = threadIdx.x & 31;
    if (w >= V) return;
    int sg = g_seg[w];
    const float* R = g_R + (size_t)sg * 192;
    float p = 0.f;
    {
        __half2 yp = *reinterpret_cast<const __half2*>(&g_Y2h[(size_t)w * 64 + 2 * l]);
        float y0 = __low2float(yp), y1 = __high2float(yp);
        int ca = 2 * l, cb = 2 * l + 1;
        float h0 = fmaxf(fmaf(y0, g_bn2[ca], g_bn2[64 + ca]), 0.f);
        float h1 = fmaxf(fmaf(y1, g_bn2[cb], g_bn2[64 + cb]), 0.f);
        p = fmaf(h0, __ldg(&R[ca]), p);
        p = fmaf(h1, __ldg(&R[cb]), p);
    }
#pragma unroll
    for (int j = 0; j < 4; ++j) {
        int c = l + 32 * j;
        p = fmaf(xmod[(size_t)w * 128 + c], __ldg(&R[64 + c]), p);
    }
#pragma unroll
    for (int o = 16; o; o >>= 1) p += __shfl_xor_sync(0xffffffffu, p, o);
    if (l == 0) g_X[w] = p + g_c[sg];
}

// ---- per-segment scaled softmax + weighted max-pool + gate ----------------
__global__ __launch_bounds__(256) void k_pool(const int* __restrict__ csr,
                                              const float* __restrict__ xmod,
                                              float* __restrict__ out,
                                              int N, int hasSeen) {
    int warp = (blockIdx.x * blockDim.x + threadIdx.x) >> 5;
    int lane = threadIdx.x & 31;
    if (warp >= N) return;
    int s = csr[warp], e = csr[warp + 1];
    int cnt = e - s;
    float* orow = out + (size_t)warp * 128;
    if (cnt <= 0) {
        orow[lane] = 0.f; orow[lane + 32] = 0.f;
        orow[lane + 64] = 0.f; orow[lane + 96] = 0.f;
        if (hasSeen && lane == 0) out[(size_t)N * 128 + warp] = 0.f;
        return;
    }
    const float NEG_INF = __int_as_float(0xff800000);
    float m = NEG_INF;
    for (int v = s + lane; v < e; v += 32) m = fmaxf(m, g_X[v]);
#pragma unroll
    for (int o = 16; o; o >>= 1) m = fmaxf(m, __shfl_xor_sync(0xffffffffu, m, o));
    float inv = rsqrtf((float)cnt);
    float ss = 0.f;
    for (int v = s + lane; v < e; v += 32) ss += expf((g_X[v] - m) * inv);
#pragma unroll
    for (int o = 16; o; o >>= 1) ss += __shfl_xor_sync(0xffffffffu, ss, o);
    float rden = 1.0f / (ss + 1e-12f);
    float G = tanhf(fmaxf(m, 0.f));
    float p0 = NEG_INF, p1 = NEG_INF, p2 = NEG_INF, p3 = NEG_INF;
    int v = s;
    for (; v + 1 < e; v += 2) {
        float a0 = expf((g_X[v] - m) * inv) * rden;
        float a1 = expf((g_X[v + 1] - m) * inv) * rden;
        const float* x0 = xmod + (size_t)v * 128;
        const float* x1 = x0 + 128;
        float u0 = x0[lane], u1 = x0[lane + 32], u2 = x0[lane + 64], u3 = x0[lane + 96];
        float w0 = x1[lane], w1 = x1[lane + 32], w2 = x1[lane + 64], w3 = x1[lane + 96];
        p0 = fmaxf(p0, fmaxf(u0 * a0, w0 * a1));
        p1 = fmaxf(p1, fmaxf(u1 * a0, w1 * a1));
        p2 = fmaxf(p2, fmaxf(u2 * a0, w2 * a1));
        p3 = fmaxf(p3, fmaxf(u3 * a0, w3 * a1));
    }
    if (v < e) {
        float a = expf((g_X[v] - m) * inv) * rden;
        const float* xr = xmod + (size_t)v * 128;
        p0 = fmaxf(p0, xr[lane] * a);
        p1 = fmaxf(p1, xr[lane + 32] * a);
        p2 = fmaxf(p2, xr[lane + 64] * a);
        p3 = fmaxf(p3, xr[lane + 96] * a);
    }
    orow[lane]      = p0 * G;
    orow[lane + 32] = p1 * G;
    orow[lane + 64] = p2 * G;
    orow[lane + 96] = p3 * G;
    if (hasSeen && lane == 0) out[(size_t)N * 128 + warp] = 1.f;
}

// ---------------------------------------------------------------------------
extern "C" void kernel_launch(void* const* d_in, const int* in_sizes, int n_in,
                              void* d_out, int out_size) {
    const float* x_main = (const float*)d_in[0];
    const float* x_mod  = (const float*)d_in[1];
    const float* x_proj = (const float*)d_in[2];
    const int*   csr    = (const int*)d_in[3];
    const float* Wq = (const float*)d_in[4];
    const float* bq = (const float*)d_in[5];
    const float* W1 = (const float*)d_in[6];
    const float* b1 = (const float*)d_in[7];
    const float* g1 = (const float*)d_in[8];
    const float* be1 = (const float*)d_in[9];
    const float* W2 = (const float*)d_in[10];
    const float* b2 = (const float*)d_in[11];
    const float* g2 = (const float*)d_in[12];
    const float* be2 = (const float*)d_in[13];
    const float* Wk = (const float*)d_in[14];
    const float* bk = (const float*)d_in[15];

    int N = in_sizes[0] / 64;
    int V = in_sizes[1] / 128;
    float* out = (float*)d_out;
    int hasSeen = (out_size >= N * 129) ? 1 : 0;
    float invV = 1.0f / (float)V;

    int vb128 = (V + 127) / 128;
    int nb128 = (N + 127) / 128;
    int segBlocks = (N + 255) / 256;

    k_seg<<<segBlocks + 4, 256>>>(csr, N, segBlocks);
    k_prep<<<1, 256>>>(Wq, bq, Wk, bk);
    k_cov<<<(V + 511) / 512, 256>>>(x_proj, V);
    k_fin1<<<1, 64>>>(W1, b1, g1, be1, invV);
    k_fused12<<<vb128, 128>>>(x_proj, b1, W1, W2, b2, V);
    k_finalize2<<<1, 64>>>(g2, be2, invV);
    {
        dim3 g(nb128, 3);
        k_R<<<g, 128>>>(x_main, N);
    }
    k_c<<<(N * 32 + 255) / 256, 256>>>(x_main, N);
    k_score<<<(V * 32 + 255) / 256, 256>>>(x_mod, V);
    k_pool<<<(N * 32 + 255) / 256, 256>>>(csr, x_mod, out, N, hasSeen);
}